// round 4
// baseline (speedup 1.0000x reference)
#include <cuda_runtime.h>

#define B    2048
#define NC   32
#define M    496
#define H1   64
#define H2   32
#define CLS  10
#define EPS  1e-5f
#define MPB  4                 // modules per block
#define MG   (M / MPB)         // 124 m-groups

__global__ __launch_bounds__(256) void nam_fused_kernel(
    const float* __restrict__ x,
    const float* __restrict__ W1, const float* __restrict__ b1,
    const float* __restrict__ g1, const float* __restrict__ be1,
    const float* __restrict__ m1, const float* __restrict__ v1,
    const float* __restrict__ W2, const float* __restrict__ b2,
    const float* __restrict__ g2, const float* __restrict__ be2,
    const float* __restrict__ m2, const float* __restrict__ v2,
    const float* __restrict__ W3, const float* __restrict__ b3,
    const float* __restrict__ Wout,
    float* __restrict__ out)
{
    const int tid    = threadIdx.x;
    const int b      = blockIdx.y * 256 + tid;
    const int m_base = blockIdx.x * MPB;

    __shared__ __align__(16) float W2t[H1 * H2];   // [k][o] transposed
    __shared__ float As[H1], Bs[H1], Cs[H1];       // folded layer-1 affine (BN1 fused)
    __shared__ float Ds[H2], Es[H2], W3s[H2];      // folded BN2 + output weights
    __shared__ float wouts[CLS];                   // Wout[:, m]
    __shared__ float b3s;
    __shared__ int   sia, sib;

    float acch[CLS];
    #pragma unroll
    for (int c = 0; c < CLS; c++) acch[c] = 0.0f;

    for (int mi = 0; mi < MPB; mi++) {
        const int m = m_base + mi;

        // ---- stage weights for module m ----
        if (tid < H1) {
            const int o = tid;
            const float s = g1[m*H1 + o] * rsqrtf(v1[m*H1 + o] + EPS);
            As[o] = s * W1[(m*H1 + o)*2 + 0];
            Bs[o] = s * W1[(m*H1 + o)*2 + 1];
            Cs[o] = s * (b1[m*H1 + o] - m1[m*H1 + o]) + be1[m*H1 + o];
        } else if (tid < H1 + H2) {
            const int o = tid - H1;
            const float s = g2[m*H2 + o] * rsqrtf(v2[m*H2 + o] + EPS);
            Ds[o]  = s;
            Es[o]  = s * (b2[m*H2 + o] - m2[m*H2 + o]) + be2[m*H2 + o];
            W3s[o] = W3[m*H2 + o];
        } else if (tid < H1 + H2 + CLS) {
            const int c = tid - (H1 + H2);
            wouts[c] = Wout[c * M + m];
        } else if (tid == H1 + H2 + CLS) {
            // m-th pair of combinations(range(32), 2), lexicographic
            int rem = m, i = 0;
            while (rem >= NC - 1 - i) { rem -= NC - 1 - i; i++; }
            sia = i;
            sib = i + 1 + rem;
            b3s = b3[m];
        }
        #pragma unroll
        for (int r = 0; r < (H1 * H2) / 256; r++) {
            const int idx = tid + r * 256;
            const int o = idx / H1;
            const int k = idx % H1;
            W2t[k * H2 + o] = W2[m * (H2 * H1) + idx];
        }
        __syncthreads();

        // ---- compute module m for this thread's batch row ----
        const float xa = __ldg(&x[b * NC + sia]);
        const float xb = __ldg(&x[b * NC + sib]);

        float acc[H2];
        #pragma unroll
        for (int o = 0; o < H2; o++) acc[o] = 0.0f;

        #pragma unroll 4
        for (int k = 0; k < H1; k++) {
            const float h1k = fmaxf(fmaf(As[k], xa, fmaf(Bs[k], xb, Cs[k])), 0.0f);
            const float4* w4 = reinterpret_cast<const float4*>(&W2t[k * H2]);
            #pragma unroll
            for (int o4 = 0; o4 < H2 / 4; o4++) {
                const float4 w = w4[o4];
                acc[o4*4 + 0] = fmaf(w.x, h1k, acc[o4*4 + 0]);
                acc[o4*4 + 1] = fmaf(w.y, h1k, acc[o4*4 + 1]);
                acc[o4*4 + 2] = fmaf(w.z, h1k, acc[o4*4 + 2]);
                acc[o4*4 + 3] = fmaf(w.w, h1k, acc[o4*4 + 3]);
            }
        }

        float res = b3s;
        #pragma unroll
        for (int o = 0; o < H2; o++)
            res += W3s[o] * fmaxf(fmaf(Ds[o], acc[o], Es[o]), 0.0f);

        // ---- head contribution, accumulated in registers ----
        #pragma unroll
        for (int c = 0; c < CLS; c++)
            acch[c] = fmaf(res, wouts[c], acch[c]);

        __syncthreads();   // protect smem before next module overwrites it
    }

    #pragma unroll
    for (int c = 0; c < CLS; c++)
        atomicAdd(&out[b * CLS + c], acch[c]);
}

// Initialize out[b][c] = bout[c] (out is poisoned by the harness).
__global__ __launch_bounds__(256) void head_init_kernel(
    const float* __restrict__ bout, float* __restrict__ out)
{
    const int i = blockIdx.x * 256 + threadIdx.x;
    if (i < B * CLS) out[i] = bout[i % CLS];
}

extern "C" void kernel_launch(void* const* d_in, const int* in_sizes, int n_in,
                              void* d_out, int out_size)
{
    // metadata order: x, pair_idx, W1, b1, g1, be1, m1, v1,
    //                 W2, b2, g2, be2, m2, v2, W3, b3, Wout, bout
    const float* x    = (const float*)d_in[0];
    // d_in[1] = pair_idx — intentionally unused (computed analytically on device)
    const float* W1   = (const float*)d_in[2];
    const float* b1   = (const float*)d_in[3];
    const float* g1   = (const float*)d_in[4];
    const float* be1  = (const float*)d_in[5];
    const float* m1   = (const float*)d_in[6];
    const float* v1   = (const float*)d_in[7];
    const float* W2   = (const float*)d_in[8];
    const float* b2   = (const float*)d_in[9];
    const float* g2   = (const float*)d_in[10];
    const float* be2  = (const float*)d_in[11];
    const float* m2   = (const float*)d_in[12];
    const float* v2   = (const float*)d_in[13];
    const float* W3   = (const float*)d_in[14];
    const float* b3   = (const float*)d_in[15];
    const float* Wout = (const float*)d_in[16];
    const float* bout = (const float*)d_in[17];
    float* out = (float*)d_out;

    head_init_kernel<<<(B * CLS + 255) / 256, 256>>>(bout, out);

    dim3 grid(MG, B / 256);
    nam_fused_kernel<<<grid, 256>>>(x, W1, b1, g1, be1, m1, v1,
                                    W2, b2, g2, be2, m2, v2, W3, b3,
                                    Wout, out);
}